// round 5
// baseline (speedup 1.0000x reference)
#include <cuda_runtime.h>

#define T_STEPS 65536
#define CHUNK   4
#define WARMUP  64
#define NSTEP   (WARMUP + CHUNK)
#define NCHUNK  (T_STEPS / CHUNK)     // 16384 chunks, one thread each
#define BLOCKT  128
#define GRIDB   (NCHUNK / BLOCKT)     // 128 blocks -> 1 per SM, 1 warp per SMSP

// Precomputed per-step constants: c1[4], c2[4] per t (+1 row pad for prefetch)
__device__ float g_c12[(T_STEPS + 1) * 8];

// MUFU.TANH — single-op tanh on sm_75+
__device__ __forceinline__ float ftanh(float x) {
    float r; asm("tanh.approx.f32 %0, %1;" : "=f"(r) : "f"(x)); return r;
}
__device__ __forceinline__ float fsigm(float x) { return fmaf(0.5f, ftanh(0.5f * x), 0.5f); }
__device__ __forceinline__ float fsilu(float x) { float h = 0.5f * x; return fmaf(h, ftanh(h), h); }

// ---------------------------------------------------------------------------
__global__ void precompute_kernel(const float* __restrict__ x,
                                  const float* __restrict__ W1, const float* __restrict__ b1,
                                  const float* __restrict__ cv1w, const float* __restrict__ cv1b,
                                  const float* __restrict__ cv2w, const float* __restrict__ cv2b) {
    int t = blockIdx.x * blockDim.x + threadIdx.x;
    if (t >= T_STEPS) return;
    float x0 = x[2 * t], x1 = x[2 * t + 1];
    float a[24];
#pragma unroll
    for (int j = 0; j < 24; ++j) {
        float v = fmaf(W1[2 * j], x0, fmaf(W1[2 * j + 1], x1, b1[j]));
        a[j] = fmaxf(v, 0.f);
    }
#pragma unroll
    for (int i = 0; i < 4; ++i) {
        float c1 = cv1b[i], c2 = cv2b[i];
#pragma unroll
        for (int j = 0; j < 24; ++j) {
            c1 = fmaf(cv1w[i * 32 + 4 + j], a[j], c1);
            c2 = fmaf(cv2w[i * 32 + 4 + j], a[j], c2);
        }
        g_c12[t * 8 + i]     = c1;
        g_c12[t * 8 + 4 + i] = c2;
    }
}

// ---- shared-memory weight layout (float offsets; all rows 16B-aligned) ----
#define SM_M1   0
#define SM_M2   16
#define SM_C3   32
#define SM_C4   48
#define SM_A5   64
#define SM_B5   80
#define SM_C6   96
#define SM_C7   112   // 4x8
#define SM_WI   144   // 12x4: rows 0-3 = i-gate, 4-7 = g-gate, 8-11 = o-gate
#define SM_W3   192   // 4x16
#define SM_W4   256   // 4x8
#define SM_W5   288   // 4x8
#define SM_C3B  320
#define SM_C4B  324
#define SM_C5B  328
#define SM_C6B  332
#define SM_C7B  336
#define SM_BI   340   // 12
#define SM_B3B  352
#define SM_B4B  356
#define SM_B5B  360
#define SM_TOT  364

__device__ __forceinline__ float dot4b(float4 w, float a, float b, float c, float d, float bias) {
    float u = fmaf(w.x, a, bias);
    u = fmaf(w.y, b, u);
    float v = w.z * c;
    v = fmaf(w.w, d, v);
    return u + v;
}

// ---------------------------------------------------------------------------
// One thread per chunk: whole 4-wide recurrence scalar-unrolled in registers.
// Weights live in smem (uniform broadcast LDS.128, hoistable by ptxas).
// ---------------------------------------------------------------------------
__global__ void __launch_bounds__(BLOCKT)
scan_kernel(const float* __restrict__ cv1w, const float* __restrict__ cv2w,
            const float* __restrict__ cv3w, const float* __restrict__ cv3b,
            const float* __restrict__ cv4w, const float* __restrict__ cv4b,
            const float* __restrict__ cv5w, const float* __restrict__ cv5b,
            const float* __restrict__ cv6w, const float* __restrict__ cv6b,
            const float* __restrict__ cv7w, const float* __restrict__ cv7b,
            const float* __restrict__ Wih,  const float* __restrict__ bih,
            const float* __restrict__ bhh,
            const float* __restrict__ W3,   const float* __restrict__ b3,
            const float* __restrict__ W4,   const float* __restrict__ b4,
            const float* __restrict__ W5,   const float* __restrict__ b5,
            float* __restrict__ out) {
    __shared__ float sm[SM_TOT];
    const int tid = threadIdx.x;

    if (tid < 4) {
        const int i = tid;
#pragma unroll
        for (int j = 0; j < 4; ++j) {
            sm[SM_M1 + i * 4 + j] = cv1w[i * 32 + 28 + j];
            sm[SM_M2 + i * 4 + j] = cv2w[i * 32 + 28 + j];
            sm[SM_C3 + i * 4 + j] = cv3w[i * 4 + j];
            sm[SM_C4 + i * 4 + j] = cv4w[i * 4 + j];
            sm[SM_A5 + i * 4 + j] = cv5w[i * 16 + j];
            sm[SM_B5 + i * 4 + j] = cv5w[i * 16 + 4 + j] + cv5w[i * 16 + 8 + j] + cv5w[i * 16 + 12 + j];
            sm[SM_C6 + i * 4 + j] = cv6w[i * 4 + j];
            sm[SM_WI + i * 4 + j]       = Wih[i * 8 + j];          // i-gate
            sm[SM_WI + (4 + i) * 4 + j] = Wih[(8 + i) * 8 + j];    // g-gate
            sm[SM_WI + (8 + i) * 4 + j] = Wih[(12 + i) * 8 + j];   // o-gate
        }
#pragma unroll
        for (int j = 0; j < 8; ++j) {
            sm[SM_C7 + i * 8 + j] = cv7w[i * 8 + j];
            sm[SM_W4 + i * 8 + j] = W4[i * 8 + j];
            sm[SM_W5 + i * 8 + j] = W5[i * 8 + j];
        }
#pragma unroll
        for (int j = 0; j < 16; ++j) sm[SM_W3 + i * 16 + j] = W3[i * 16 + j];
        sm[SM_C3B + i] = cv3b[i];
        sm[SM_C4B + i] = cv4b[i];
        sm[SM_C5B + i] = cv5b[i];
        sm[SM_C6B + i] = cv6b[i];
        sm[SM_C7B + i] = cv7b[i];
        sm[SM_BI + i]     = bih[i]      + bhh[i];
        sm[SM_BI + 4 + i] = bih[8 + i]  + bhh[8 + i];
        sm[SM_BI + 8 + i] = bih[12 + i] + bhh[12 + i];
        sm[SM_B3B + i] = b3[i];
        sm[SM_B4B + i] = b4[i];
        sm[SM_B5B + i] = b5[i];
    }
    __syncthreads();

    const float4* smv = (const float4*)sm;
    const int chunk  = blockIdx.x * BLOCKT + tid;
    const int pay_lo = chunk * CHUNK;
    const int pay_hi = pay_lo + CHUNK;
    int start = pay_lo - WARMUP;
    if (start < 0) start = 0;

    const float SC = 0.70710678118654752f;  // 1/sqrt(2)

    float P0 = 0.f, Pa = 0.f, Pb = 0.f, Pc = 0.f;
    const float4* c12 = (const float4*)g_c12;
    float4 c1 = c12[start * 2];
    float4 c2 = c12[start * 2 + 1];

    for (int it = 0; it < NSTEP; ++it) {
        const int t = start + it;
        float4 c1n = c12[(t + 1) * 2];
        float4 c2n = c12[(t + 1) * 2 + 1];

        // x1 = silu(M1 @ P + c1), y2 = silu(M2 @ P + c2)
        float x10 = fsilu(dot4b(smv[SM_M1 / 4 + 0], P0, Pa, Pb, Pc, c1.x));
        float x11 = fsilu(dot4b(smv[SM_M1 / 4 + 1], P0, Pa, Pb, Pc, c1.y));
        float x12 = fsilu(dot4b(smv[SM_M1 / 4 + 2], P0, Pa, Pb, Pc, c1.z));
        float x13 = fsilu(dot4b(smv[SM_M1 / 4 + 3], P0, Pa, Pb, Pc, c1.w));
        float y20 = fsilu(dot4b(smv[SM_M2 / 4 + 0], P0, Pa, Pb, Pc, c2.x));
        float y21 = fsilu(dot4b(smv[SM_M2 / 4 + 1], P0, Pa, Pb, Pc, c2.y));
        float y22 = fsilu(dot4b(smv[SM_M2 / 4 + 2], P0, Pa, Pb, Pc, c2.z));
        float y23 = fsilu(dot4b(smv[SM_M2 / 4 + 3], P0, Pa, Pb, Pc, c2.w));

        // x3 = silu(C3 @ x1)
        float x30 = fsilu(dot4b(smv[SM_C3 / 4 + 0], x10, x11, x12, x13, sm[SM_C3B + 0]));
        float x31 = fsilu(dot4b(smv[SM_C3 / 4 + 1], x10, x11, x12, x13, sm[SM_C3B + 1]));
        float x32 = fsilu(dot4b(smv[SM_C3 / 4 + 2], x10, x11, x12, x13, sm[SM_C3B + 2]));
        float x33 = fsilu(dot4b(smv[SM_C3 / 4 + 3], x10, x11, x12, x13, sm[SM_C3B + 3]));

        // x4 = silu(C4 @ x3)
        float x40 = fsilu(dot4b(smv[SM_C4 / 4 + 0], x30, x31, x32, x33, sm[SM_C4B + 0]));
        float x41 = fsilu(dot4b(smv[SM_C4 / 4 + 1], x30, x31, x32, x33, sm[SM_C4B + 1]));
        float x42 = fsilu(dot4b(smv[SM_C4 / 4 + 2], x30, x31, x32, x33, sm[SM_C4B + 2]));
        float x43 = fsilu(dot4b(smv[SM_C4 / 4 + 3], x30, x31, x32, x33, sm[SM_C4B + 3]));

        // t5 = silu(A5 @ x4 + B5 @ relu(x4) + c5b)
        float r0 = fmaxf(x40, 0.f), r1 = fmaxf(x41, 0.f), r2 = fmaxf(x42, 0.f), r3 = fmaxf(x43, 0.f);
        float t50 = fsilu(dot4b(smv[SM_A5 / 4 + 0], x40, x41, x42, x43, sm[SM_C5B + 0])
                        + dot4b(smv[SM_B5 / 4 + 0], r0, r1, r2, r3, 0.f));
        float t51 = fsilu(dot4b(smv[SM_A5 / 4 + 1], x40, x41, x42, x43, sm[SM_C5B + 1])
                        + dot4b(smv[SM_B5 / 4 + 1], r0, r1, r2, r3, 0.f));
        float t52 = fsilu(dot4b(smv[SM_A5 / 4 + 2], x40, x41, x42, x43, sm[SM_C5B + 2])
                        + dot4b(smv[SM_B5 / 4 + 2], r0, r1, r2, r3, 0.f));
        float t53 = fsilu(dot4b(smv[SM_A5 / 4 + 3], x40, x41, x42, x43, sm[SM_C5B + 3])
                        + dot4b(smv[SM_B5 / 4 + 3], r0, r1, r2, r3, 0.f));

        // y1 = silu(C6 @ t5)
        float y10 = fsilu(dot4b(smv[SM_C6 / 4 + 0], t50, t51, t52, t53, sm[SM_C6B + 0]));
        float y11 = fsilu(dot4b(smv[SM_C6 / 4 + 1], t50, t51, t52, t53, sm[SM_C6B + 1]));
        float y12 = fsilu(dot4b(smv[SM_C6 / 4 + 2], t50, t51, t52, t53, sm[SM_C6B + 2]));
        float y13 = fsilu(dot4b(smv[SM_C6 / 4 + 3], t50, t51, t52, t53, sm[SM_C6B + 3]));

        // P1 = silu(C7 @ [y1; y2])
        float q0 = fsilu(dot4b(smv[SM_C7 / 4 + 0], y10, y11, y12, y13, sm[SM_C7B + 0])
                       + dot4b(smv[SM_C7 / 4 + 1], y20, y21, y22, y23, 0.f));
        float q1 = fsilu(dot4b(smv[SM_C7 / 4 + 2], y10, y11, y12, y13, sm[SM_C7B + 1])
                       + dot4b(smv[SM_C7 / 4 + 3], y20, y21, y22, y23, 0.f));
        float q2 = fsilu(dot4b(smv[SM_C7 / 4 + 4], y10, y11, y12, y13, sm[SM_C7B + 2])
                       + dot4b(smv[SM_C7 / 4 + 5], y20, y21, y22, y23, 0.f));
        float q3 = fsilu(dot4b(smv[SM_C7 / 4 + 6], y10, y11, y12, y13, sm[SM_C7B + 3])
                       + dot4b(smv[SM_C7 / 4 + 7], y20, y21, y22, y23, 0.f));

        // LSTM single step from zero state (forget gate dead)
        float gi0 = dot4b(smv[SM_WI / 4 + 0], q0, q1, q2, q3, sm[SM_BI + 0]);
        float gi1 = dot4b(smv[SM_WI / 4 + 1], q0, q1, q2, q3, sm[SM_BI + 1]);
        float gi2 = dot4b(smv[SM_WI / 4 + 2], q0, q1, q2, q3, sm[SM_BI + 2]);
        float gi3 = dot4b(smv[SM_WI / 4 + 3], q0, q1, q2, q3, sm[SM_BI + 3]);
        float gg0 = dot4b(smv[SM_WI / 4 + 4], q0, q1, q2, q3, sm[SM_BI + 4]);
        float gg1 = dot4b(smv[SM_WI / 4 + 5], q0, q1, q2, q3, sm[SM_BI + 5]);
        float gg2 = dot4b(smv[SM_WI / 4 + 6], q0, q1, q2, q3, sm[SM_BI + 6]);
        float gg3 = dot4b(smv[SM_WI / 4 + 7], q0, q1, q2, q3, sm[SM_BI + 7]);
        float go0 = dot4b(smv[SM_WI / 4 + 8], q0, q1, q2, q3, sm[SM_BI + 8]);
        float go1 = dot4b(smv[SM_WI / 4 + 9], q0, q1, q2, q3, sm[SM_BI + 9]);
        float go2 = dot4b(smv[SM_WI / 4 + 10], q0, q1, q2, q3, sm[SM_BI + 10]);
        float go3 = dot4b(smv[SM_WI / 4 + 11], q0, q1, q2, q3, sm[SM_BI + 11]);
        float cc0 = fsigm(gi0) * ftanh(gg0);
        float cc1 = fsigm(gi1) * ftanh(gg1);
        float cc2 = fsigm(gi2) * ftanh(gg2);
        float cc3 = fsigm(gi3) * ftanh(gg3);
        float S00 = fsigm(go0) * ftanh(cc0);
        float S01 = fsigm(go1) * ftanh(cc1);
        float S02 = fsigm(go2) * ftanh(cc2);
        float S03 = fsigm(go3) * ftanh(cc3);

        // chan_att(S0, 2): softmax of 2 == sigmoid of scaled diff; S[1]=1-S[0]
        float d00 = fmaf(S00, S00, S01 * S01);
        float d01 = fmaf(S00, S02, S01 * S03);
        float d11 = fmaf(S02, S02, S03 * S03);
        float Sv0 = fsigm(SC * (d00 - d01));
        float Sv1 = 1.f - Sv0;
        float Sv2 = fsigm(SC * (d01 - d11));
        float Sv3 = 1.f - Sv2;

        // chan_att([P1; S], 4): rows (q0,q1),(q2,q3),(Sv0,Sv1),(Sv2,Sv3); Gram symmetric
        float g00 = fmaf(q0, q0, q1 * q1);
        float g01 = fmaf(q0, q2, q1 * q3);
        float g02 = fmaf(q0, Sv0, q1 * Sv1);
        float g03 = fmaf(q0, Sv2, q1 * Sv3);
        float g11 = fmaf(q2, q2, q3 * q3);
        float g12 = fmaf(q2, Sv0, q3 * Sv1);
        float g13 = fmaf(q2, Sv2, q3 * Sv3);
        float g22 = fmaf(Sv0, Sv0, Sv1 * Sv1);
        float g23 = fmaf(Sv0, Sv2, Sv1 * Sv3);
        float g33 = fmaf(Sv2, Sv2, Sv3 * Sv3);
        float z00 = __expf(SC * g00), z01 = __expf(SC * g01), z02 = __expf(SC * g02), z03 = __expf(SC * g03);
        float z11 = __expf(SC * g11), z12 = __expf(SC * g12), z13 = __expf(SC * g13);
        float z22 = __expf(SC * g22), z23 = __expf(SC * g23), z33 = __expf(SC * g33);
        float i0 = __fdividef(1.f, (z00 + z01) + (z02 + z03));
        float i1 = __fdividef(1.f, (z01 + z11) + (z12 + z13));
        float i2 = __fdividef(1.f, (z02 + z12) + (z22 + z23));
        float i3 = __fdividef(1.f, (z03 + z13) + (z23 + z33));
        float K0  = z00 * i0, K1  = z01 * i0, K2  = z02 * i0, K3  = z03 * i0;
        float K4  = z01 * i1, K5  = z11 * i1, K6  = z12 * i1, K7  = z13 * i1;
        float K8  = z02 * i2, K9  = z12 * i2, K10 = z22 * i2, K11 = z23 * i2;
        float K12 = z03 * i3, K13 = z13 * i3, K14 = z23 * i3, K15 = z33 * i3;

        // Kt = relu(W3 @ K16 + b3)
        float kt0, kt1, kt2, kt3;
        {
            float a, b;
            a = dot4b(smv[SM_W3 / 4 + 0], K0, K1, K2, K3, sm[SM_B3B + 0])
              + dot4b(smv[SM_W3 / 4 + 1], K4, K5, K6, K7, 0.f);
            b = dot4b(smv[SM_W3 / 4 + 2], K8, K9, K10, K11, 0.f)
              + dot4b(smv[SM_W3 / 4 + 3], K12, K13, K14, K15, 0.f);
            kt0 = fmaxf(a + b, 0.f);
            a = dot4b(smv[SM_W3 / 4 + 4], K0, K1, K2, K3, sm[SM_B3B + 1])
              + dot4b(smv[SM_W3 / 4 + 5], K4, K5, K6, K7, 0.f);
            b = dot4b(smv[SM_W3 / 4 + 6], K8, K9, K10, K11, 0.f)
              + dot4b(smv[SM_W3 / 4 + 7], K12, K13, K14, K15, 0.f);
            kt1 = fmaxf(a + b, 0.f);
            a = dot4b(smv[SM_W3 / 4 + 8], K0, K1, K2, K3, sm[SM_B3B + 2])
              + dot4b(smv[SM_W3 / 4 + 9], K4, K5, K6, K7, 0.f);
            b = dot4b(smv[SM_W3 / 4 + 10], K8, K9, K10, K11, 0.f)
              + dot4b(smv[SM_W3 / 4 + 11], K12, K13, K14, K15, 0.f);
            kt2 = fmaxf(a + b, 0.f);
            a = dot4b(smv[SM_W3 / 4 + 12], K0, K1, K2, K3, sm[SM_B3B + 3])
              + dot4b(smv[SM_W3 / 4 + 13], K4, K5, K6, K7, 0.f);
            b = dot4b(smv[SM_W3 / 4 + 14], K8, K9, K10, K11, 0.f)
              + dot4b(smv[SM_W3 / 4 + 15], K12, K13, K14, K15, 0.f);
            kt3 = fmaxf(a + b, 0.f);
        }

        // o4 = relu(W4 @ [S; Kt] + b4)
        float o40 = fmaxf(dot4b(smv[SM_W4 / 4 + 0], Sv0, Sv1, Sv2, Sv3, sm[SM_B4B + 0])
                        + dot4b(smv[SM_W4 / 4 + 1], kt0, kt1, kt2, kt3, 0.f), 0.f);
        float o41 = fmaxf(dot4b(smv[SM_W4 / 4 + 2], Sv0, Sv1, Sv2, Sv3, sm[SM_B4B + 1])
                        + dot4b(smv[SM_W4 / 4 + 3], kt0, kt1, kt2, kt3, 0.f), 0.f);
        float o42 = fmaxf(dot4b(smv[SM_W4 / 4 + 4], Sv0, Sv1, Sv2, Sv3, sm[SM_B4B + 2])
                        + dot4b(smv[SM_W4 / 4 + 5], kt0, kt1, kt2, kt3, 0.f), 0.f);
        float o43 = fmaxf(dot4b(smv[SM_W4 / 4 + 6], Sv0, Sv1, Sv2, Sv3, sm[SM_B4B + 3])
                        + dot4b(smv[SM_W4 / 4 + 7], kt0, kt1, kt2, kt3, 0.f), 0.f);

        // P = relu(W5 @ [P1; o4] + b5)
        P0 = fmaxf(dot4b(smv[SM_W5 / 4 + 0], q0, q1, q2, q3, sm[SM_B5B + 0])
                 + dot4b(smv[SM_W5 / 4 + 1], o40, o41, o42, o43, 0.f), 0.f);
        Pa = fmaxf(dot4b(smv[SM_W5 / 4 + 2], q0, q1, q2, q3, sm[SM_B5B + 1])
                 + dot4b(smv[SM_W5 / 4 + 3], o40, o41, o42, o43, 0.f), 0.f);
        Pb = fmaxf(dot4b(smv[SM_W5 / 4 + 4], q0, q1, q2, q3, sm[SM_B5B + 2])
                 + dot4b(smv[SM_W5 / 4 + 5], o40, o41, o42, o43, 0.f), 0.f);
        Pc = fmaxf(dot4b(smv[SM_W5 / 4 + 6], q0, q1, q2, q3, sm[SM_B5B + 3])
                 + dot4b(smv[SM_W5 / 4 + 7], o40, o41, o42, o43, 0.f), 0.f);

        if (t >= pay_lo && t < pay_hi) {
            float4 kt4 = make_float4(kt0, kt1, kt2, kt3);
            *(float4*)(out + t * 4) = kt4;
        }

        c1 = c1n;
        c2 = c2n;
    }
}

// ---------------------------------------------------------------------------
extern "C" void kernel_launch(void* const* d_in, const int* in_sizes, int n_in,
                              void* d_out, int out_size) {
    const float* x    = (const float*)d_in[0];
    const float* W1   = (const float*)d_in[1];
    const float* b1   = (const float*)d_in[2];
    const float* cv1w = (const float*)d_in[3];
    const float* cv1b = (const float*)d_in[4];
    const float* cv2w = (const float*)d_in[5];
    const float* cv2b = (const float*)d_in[6];
    const float* cv3w = (const float*)d_in[7];
    const float* cv3b = (const float*)d_in[8];
    const float* cv4w = (const float*)d_in[9];
    const float* cv4b = (const float*)d_in[10];
    const float* cv5w = (const float*)d_in[11];
    const float* cv5b = (const float*)d_in[12];
    const float* cv6w = (const float*)d_in[13];
    const float* cv6b = (const float*)d_in[14];
    const float* cv7w = (const float*)d_in[15];
    const float* cv7b = (const float*)d_in[16];
    const float* Wih  = (const float*)d_in[17];
    const float* bih  = (const float*)d_in[18];
    const float* bhh  = (const float*)d_in[19];
    const float* W3   = (const float*)d_in[20];
    const float* b3   = (const float*)d_in[21];
    const float* W4   = (const float*)d_in[22];
    const float* b4   = (const float*)d_in[23];
    const float* W5   = (const float*)d_in[24];
    const float* b5   = (const float*)d_in[25];
    float* out = (float*)d_out;

    precompute_kernel<<<T_STEPS / 256, 256>>>(x, W1, b1, cv1w, cv1b, cv2w, cv2b);
    scan_kernel<<<GRIDB, BLOCKT>>>(cv1w, cv2w, cv3w, cv3b, cv4w, cv4b, cv5w, cv5b,
                                   cv6w, cv6b, cv7w, cv7b, Wih, bih, bhh,
                                   W3, b3, W4, b4, W5, b5, out);
}